// round 9
// baseline (speedup 1.0000x reference)
#include <cuda_runtime.h>

// Problem constants
#define NB   16      // batch
#define NC   64      // channels
#define NH   48      // H == W
#define ND   3072    // xLSTM feature dim (C*W)
#define ND4  12288   // 4*D
#define NT   48      // sequence length
#define NROWS 768    // B*T

// ---------------- device scratch (no allocations allowed) ----------------
__device__ float d_pre1[NROWS * ND4];     // 37.75 MB
__device__ float d_pre2[NROWS * ND4];     // 37.75 MB
__device__ float d_gTp[2 * 2 * ND4 * NB]; // [khalf][stack][col][b] partial h@R
__device__ float d_cst[2 * ND * NB];      // [stack][d][b]
__device__ float d_nst[2 * ND * NB];
__device__ float d_mst[2 * ND * NB];
__device__ float d_hT[2 * ND * NB];       // [stack][d][b]
__device__ float d_Y1[NROWS * ND];        // hidden outputs stack 1 [b][t][d]
__device__ float d_Y2[NROWS * ND];        // hidden outputs stack 2
__device__ float d_xh[NB * NC * NH];
__device__ float d_xw[NB * NC * NH];
__device__ float d_sh[NB * NC * NH];
__device__ float d_sw[NB * NC * NH];

// ---------------- packed fp32x2 helpers (Blackwell FFMA2) ----------------
__device__ __forceinline__ unsigned long long pack2(float x, float y) {
    unsigned long long r;
    asm("mov.b64 %0, {%1, %2};" : "=l"(r) : "f"(x), "f"(y));
    return r;
}
__device__ __forceinline__ void fma2(unsigned long long& c, unsigned long long a,
                                     unsigned long long b) {
    asm("fma.rn.f32x2 %0, %1, %2, %0;" : "+l"(c) : "l"(a), "l"(b));
}
__device__ __forceinline__ float2 unpack2(unsigned long long v) {
    float2 f;
    asm("mov.b64 {%0, %1}, %2;" : "=f"(f.x), "=f"(f.y) : "l"(v));
    return f;
}

// ---------------- pre-projection GEMM: pre = X @ W + bias ----------------
// A: [768, 3072] (x viewed flat), W: [3072, 12288], out: [768, 12288]
// 128x128 tile, BK=8, 256 threads, 8x8 microtile via FFMA2.
__global__ void __launch_bounds__(256) sgemm_pre(const float* __restrict__ A,
                                                 const float* __restrict__ Wm,
                                                 const float* __restrict__ bias,
                                                 int which) {
    __shared__ float As[8][128];
    __shared__ float Bs[8][128];
    float* Cout = which ? d_pre2 : d_pre1;

    int tid = threadIdx.x;
    int bm = blockIdx.y, bn = blockIdx.x;
    int arow = tid >> 1, acol = (tid & 1) << 2;
    int brow = tid >> 5, bcol = (tid & 31) << 2;
    int ty = tid >> 4, tx = tid & 15;

    unsigned long long acc[8][4];
#pragma unroll
    for (int i = 0; i < 8; i++)
#pragma unroll
        for (int j = 0; j < 4; j++) acc[i][j] = 0ull;

    const float* Ap = A + (bm * 128 + arow) * ND + acol;
    const float* Bp = Wm + brow * ND4 + bn * 128 + bcol;

    for (int k0 = 0; k0 < ND; k0 += 8) {
        float4 av = *(const float4*)(Ap + k0);
        float4 bv = *(const float4*)(Bp + (size_t)k0 * ND4);
        As[acol + 0][arow] = av.x;
        As[acol + 1][arow] = av.y;
        As[acol + 2][arow] = av.z;
        As[acol + 3][arow] = av.w;
        *(float4*)&Bs[brow][bcol] = bv;
        __syncthreads();
#pragma unroll
        for (int kk = 0; kk < 8; kk++) {
            float4 a0 = *(const float4*)&As[kk][ty * 8];
            float4 a1 = *(const float4*)&As[kk][ty * 8 + 4];
            ulonglong2 bq0 = *(const ulonglong2*)&Bs[kk][tx * 8];
            ulonglong2 bq1 = *(const ulonglong2*)&Bs[kk][tx * 8 + 4];
            unsigned long long rb[4] = {bq0.x, bq0.y, bq1.x, bq1.y};
            float aa[8] = {a0.x, a0.y, a0.z, a0.w, a1.x, a1.y, a1.z, a1.w};
#pragma unroll
            for (int i = 0; i < 8; i++) {
                unsigned long long ra = pack2(aa[i], aa[i]);
#pragma unroll
                for (int j = 0; j < 4; j++) fma2(acc[i][j], ra, rb[j]);
            }
        }
        __syncthreads();
    }

    int cbase = bn * 128 + tx * 8;
    float4 bb0 = *(const float4*)(bias + cbase);
    float4 bb1 = *(const float4*)(bias + cbase + 4);
#pragma unroll
    for (int i = 0; i < 8; i++) {
        int row = bm * 128 + ty * 8 + i;
        float2 v0 = unpack2(acc[i][0]);
        float2 v1 = unpack2(acc[i][1]);
        float2 v2 = unpack2(acc[i][2]);
        float2 v3 = unpack2(acc[i][3]);
        float4 o0 = make_float4(v0.x + bb0.x, v0.y + bb0.y, v1.x + bb0.z, v1.y + bb0.w);
        float4 o1 = make_float4(v2.x + bb1.x, v2.y + bb1.y, v3.x + bb1.z, v3.y + bb1.w);
        *(float4*)(Cout + (size_t)row * ND4 + cbase) = o0;
        *(float4*)(Cout + (size_t)row * ND4 + cbase + 4) = o1;
    }
}

// ---------------- fused recurrent step GEMM (both stacks, split-K) --------
// grid = 768 blocks: stack = bx&1; (bx>>1) = khalf*192 + coltile.
// block = 256 threads = 8 warps; warp w = k-slice of 192 within its K-half.
// Lane handles 2 consecutive columns (float2 R load, 256B/warp coalesced).
// h read from global [stack][d][b] via broadcast LDG.128 (L1-hot, 96KB/stack-half).
// Partial sums -> d_gTp[khalf][stack][col][b]; gate kernel adds the halves.
#define STEPK(rv, hq)                                                       \
    {                                                                       \
        unsigned long long rr0 = pack2((rv).x, (rv).x);                     \
        unsigned long long rr1 = pack2((rv).y, (rv).y);                     \
        ulonglong2 ha = (hq)[0], hb = (hq)[1], hc = (hq)[2], hd = (hq)[3];  \
        fma2(a0[0], rr0, ha.x); fma2(a0[1], rr0, ha.y);                     \
        fma2(a0[2], rr0, hb.x); fma2(a0[3], rr0, hb.y);                     \
        fma2(a0[4], rr0, hc.x); fma2(a0[5], rr0, hc.y);                     \
        fma2(a0[6], rr0, hd.x); fma2(a0[7], rr0, hd.y);                     \
        fma2(a1[0], rr1, ha.x); fma2(a1[1], rr1, ha.y);                     \
        fma2(a1[2], rr1, hb.x); fma2(a1[3], rr1, hb.y);                     \
        fma2(a1[4], rr1, hc.x); fma2(a1[5], rr1, hc.y);                     \
        fma2(a1[6], rr1, hd.x); fma2(a1[7], rr1, hd.y);                     \
    }

__global__ void __launch_bounds__(256) step_gemm_f(const float* __restrict__ R1,
                                                   const float* __restrict__ R2) {
    __shared__ unsigned long long sa[8][64][8];  // 32 KB
    int bx = blockIdx.x;
    int s = bx & 1;
    int tmp = bx >> 1;          // 0..383
    int kh = tmp / 192;         // K-half
    int cb = tmp - kh * 192;    // col-tile 0..191
    const float* __restrict__ R = s ? R2 : R1;
    int tid = threadIdx.x;
    int w = tid >> 5, l = tid & 31;
    int col0 = cb * 64 + l * 2;
    int kbase = kh * 1536 + w * 192;

    unsigned long long a0[8], a1[8];
#pragma unroll
    for (int j = 0; j < 8; j++) { a0[j] = 0ull; a1[j] = 0ull; }

    const float* rp = R + (size_t)kbase * ND4 + col0;
    const ulonglong2* __restrict__ hp =
        (const ulonglong2*)(d_hT + (s * ND + kbase) * NB);

#pragma unroll 1
    for (int kk = 0; kk < 192; kk += 4) {
        // batched R loads first: MLP=4 per warp toward DRAM
        float2 rv0 = __ldcs((const float2*)(rp));
        float2 rv1 = __ldcs((const float2*)(rp + ND4));
        float2 rv2 = __ldcs((const float2*)(rp + 2 * ND4));
        float2 rv3 = __ldcs((const float2*)(rp + 3 * ND4));
        rp += 4 * ND4;
        STEPK(rv0, hp);
        STEPK(rv1, hp + 4);
        STEPK(rv2, hp + 8);
        STEPK(rv3, hp + 12);
        hp += 16;
    }

#pragma unroll
    for (int j = 0; j < 8; j++) {
        sa[w][2 * l][j] = a0[j];
        sa[w][2 * l + 1][j] = a1[j];
    }
    __syncthreads();

    if (tid < 64) {
        int colg = cb * 64 + tid;
        float* g = d_gTp + ((kh * 2 + s) * ND4 + colg) * NB;
#pragma unroll
        for (int j = 0; j < 8; j++) {
            float sx = 0.f, sy = 0.f;
#pragma unroll
            for (int sl = 0; sl < 8; sl++) {
                float2 v = unpack2(sa[sl][tid][j]);
                sx += v.x;
                sy += v.y;
            }
            *(float2*)(g + 2 * j) = make_float2(sx, sy);
        }
    }
}

// ---------------- fused sLSTM gate update (both stacks) ----------------
// thread = (stack, d, b-half of 8). g = gTp[0] + gTp[1] + pre[:,t,:];
// updates states, writes hT [stack][d][b] and Y [b][t][d].
__global__ void __launch_bounds__(256) gate_step_f(int t) {
    int idx = blockIdx.x * 256 + threadIdx.x;  // 12288 threads
    int s = idx / (2 * ND);
    int r = idx - s * (2 * ND);
    int d = r >> 1;
    int b0 = (r & 1) << 3;
    const float* __restrict__ pre = s ? d_pre2 : d_pre1;
    float* __restrict__ Y = s ? d_Y2 : d_Y1;

    const int rowstep = (ND * NB) / 4;   // float4 stride between gates
    const int half = (2 * ND4 * NB) / 4; // float4 stride between K-halves
    const float4* gi = (const float4*)(d_gTp + (s * ND4 + d) * NB + b0);

    float gv[4][8];
#pragma unroll
    for (int gt = 0; gt < 4; gt++) {
        float4 p0 = gi[gt * rowstep], p1 = gi[gt * rowstep + 1];
        float4 q0 = gi[gt * rowstep + half], q1 = gi[gt * rowstep + half + 1];
        gv[gt][0] = p0.x + q0.x; gv[gt][1] = p0.y + q0.y;
        gv[gt][2] = p0.z + q0.z; gv[gt][3] = p0.w + q0.w;
        gv[gt][4] = p1.x + q1.x; gv[gt][5] = p1.y + q1.y;
        gv[gt][6] = p1.z + q1.z; gv[gt][7] = p1.w + q1.w;
    }

    int sbase = (s * ND + d) * NB + b0;
    float4 c0 = *(const float4*)(d_cst + sbase);
    float4 c1 = *(const float4*)(d_cst + sbase + 4);
    float4 n0 = *(const float4*)(d_nst + sbase);
    float4 n1 = *(const float4*)(d_nst + sbase + 4);
    float4 m0 = *(const float4*)(d_mst + sbase);
    float4 m1 = *(const float4*)(d_mst + sbase + 4);
    float cv[8] = {c0.x, c0.y, c0.z, c0.w, c1.x, c1.y, c1.z, c1.w};
    float nv[8] = {n0.x, n0.y, n0.z, n0.w, n1.x, n1.y, n1.z, n1.w};
    float mv[8] = {m0.x, m0.y, m0.z, m0.w, m1.x, m1.y, m1.z, m1.w};
    float hv[8];

#pragma unroll
    for (int j = 0; j < 8; j++) {
        int b = b0 + j;
        const float* prow = pre + (size_t)(b * NT + t) * ND4 + d;
        float it = gv[0][j] + prow[0];
        float ft = gv[1][j] + prow[ND];
        float zt = gv[2][j] + prow[2 * ND];
        float ot = gv[3][j] + prow[3 * ND];
        float m = mv[j];
        float mn = fmaxf(ft + m, it);
        float ig = expf(it - mn);
        float fg = expf(ft + m - mn);
        float cn = fg * cv[j] + ig * tanhf(zt);
        float nn = fg * nv[j] + ig;
        float h = cn / (nn + 1e-6f) * (1.0f / (1.0f + expf(-ot)));
        cv[j] = cn;
        nv[j] = nn;
        mv[j] = mn;
        hv[j] = h;
        Y[(size_t)b * (NT * ND) + t * ND + d] = h;
    }

    *(float4*)(d_cst + sbase) = make_float4(cv[0], cv[1], cv[2], cv[3]);
    *(float4*)(d_cst + sbase + 4) = make_float4(cv[4], cv[5], cv[6], cv[7]);
    *(float4*)(d_nst + sbase) = make_float4(nv[0], nv[1], nv[2], nv[3]);
    *(float4*)(d_nst + sbase + 4) = make_float4(nv[4], nv[5], nv[6], nv[7]);
    *(float4*)(d_mst + sbase) = make_float4(mv[0], mv[1], mv[2], mv[3]);
    *(float4*)(d_mst + sbase + 4) = make_float4(mv[4], mv[5], mv[6], mv[7]);
    *(float4*)(d_hT + sbase) = make_float4(hv[0], hv[1], hv[2], hv[3]);
    *(float4*)(d_hT + sbase + 4) = make_float4(hv[4], hv[5], hv[6], hv[7]);
}

__global__ void init_state() {
    int idx = blockIdx.x * 256 + threadIdx.x;  // 98304
    d_cst[idx] = 0.f;
    d_nst[idx] = 0.f;
    d_mst[idx] = 0.f;
    d_hT[idx] = 0.f;
}

// ---------------- spatial means ----------------
// xh[b,c,p] = mean_q Y2[(b*64+c)*2304 + p*48 + q]   (contiguous)
// xw[b,c,p] = mean_q Y1[(b*64+c)*2304 + q*48 + p]   (strided)
__global__ void reduce_means() {
    int bc = blockIdx.x;  // 0..1023 = b*64+c
    int p = threadIdx.x;  // 0..47
    const float* base2 = d_Y2 + bc * 2304;
    const float* base1 = d_Y1 + bc * 2304;
    float s = 0.f;
#pragma unroll 8
    for (int q = 0; q < 48; q++) s += base2[p * 48 + q];
    d_xh[bc * 48 + p] = s * (1.0f / 48.0f);
    float s2 = 0.f;
#pragma unroll 8
    for (int q = 0; q < 48; q++) s2 += base1[q * 48 + p];
    d_xw[bc * 48 + p] = s2 * (1.0f / 48.0f);
}

// ---------------- grouped conv1d + GroupNorm + sigmoid ----------------
__global__ void conv_gn(const float* __restrict__ cw, const float* __restrict__ gamma,
                        const float* __restrict__ beta) {
    int z = blockIdx.y;
    const float* u = z ? d_xw : d_xh;
    float* o = z ? d_sw : d_sh;
    int bidx = blockIdx.x;
    int b = bidx >> 4, g = bidx & 15;
    __shared__ float uin[8][52];
    __shared__ float wsh[4][8][5];
    __shared__ float svals[192];
    __shared__ float stats[2];
    int tid = threadIdx.x;
    int cg = g >> 1;  // conv group of this GN group's channels

    for (int i = tid; i < 384; i += 192) {
        int ci = i / 48, p = i - ci * 48;
        uin[ci][p + 2] = u[(b * NC + cg * 8 + ci) * 48 + p];
    }
    if (tid < 8) {
        uin[tid][0] = 0.f;
        uin[tid][1] = 0.f;
        uin[tid][50] = 0.f;
        uin[tid][51] = 0.f;
    }
    for (int i = tid; i < 160; i += 192) {
        ((float*)wsh)[i] = cw[g * 160 + i];
    }
    __syncthreads();

    int lc = tid / 48, p = tid - lc * 48;
    float v = 0.f;
#pragma unroll
    for (int ci = 0; ci < 8; ci++)
#pragma unroll
        for (int k = 0; k < 5; k++) v += uin[ci][p + k] * wsh[lc][ci][k];

    svals[tid] = v;
    __syncthreads();
    if (tid < 32) {
        float s = 0.f, s2 = 0.f;
#pragma unroll
        for (int i = 0; i < 6; i++) {
            float x = svals[tid + i * 32];
            s += x;
            s2 += x * x;
        }
#pragma unroll
        for (int off = 16; off; off >>= 1) {
            s += __shfl_xor_sync(0xffffffff, s, off);
            s2 += __shfl_xor_sync(0xffffffff, s2, off);
        }
        if (tid == 0) {
            stats[0] = s * (1.0f / 192.0f);
            stats[1] = s2 * (1.0f / 192.0f);
        }
    }
    __syncthreads();
    float mu = stats[0];
    float var = stats[1] - mu * mu;
    int co = 4 * g + lc;
    float xn = (v - mu) * rsqrtf(var + 1e-5f);
    float yv = xn * gamma[co] + beta[co];
    o[(b * NC + co) * 48 + p] = 1.0f / (1.0f + expf(-yv));
}

// ---------------- final: out[b,c,h,w] = sh[b,c,h]*sw[b,c,w]*x ----------------
__global__ void final_mul(const float* __restrict__ x, float* __restrict__ out) {
    int idx = blockIdx.x * 256 + threadIdx.x;  // 2359296 total, exact
    int b = idx / (NC * NH * NH);
    int r = idx - b * (NC * NH * NH);
    int c = r / (NH * NH);
    int r2 = r - c * (NH * NH);
    int h = r2 / NH;
    int w = r2 - h * NH;
    out[idx] = d_sh[(b * NC + c) * 48 + h] * d_sw[(b * NC + c) * 48 + w] * x[idx];
}

// ---------------- launch ----------------
extern "C" void kernel_launch(void* const* d_in, const int* in_sizes, int n_in,
                              void* d_out, int out_size) {
    const float* x  = (const float*)d_in[0];
    const float* W1 = (const float*)d_in[1];
    const float* R1 = (const float*)d_in[2];
    const float* b1 = (const float*)d_in[3];
    const float* W2 = (const float*)d_in[4];
    const float* R2 = (const float*)d_in[5];
    const float* b2 = (const float*)d_in[6];
    const float* cw = (const float*)d_in[7];
    const float* gg = (const float*)d_in[8];
    const float* gb = (const float*)d_in[9];
    float* out = (float*)d_out;

    dim3 gpre(96, 6);
    sgemm_pre<<<gpre, 256>>>(x, W1, b1, 0);
    sgemm_pre<<<gpre, 256>>>(x, W2, b2, 1);

    init_state<<<384, 256>>>();
    for (int t = 0; t < NT; t++) {
        step_gemm_f<<<768, 256>>>(R1, R2);
        gate_step_f<<<48, 256>>>(t);
    }

    reduce_means<<<1024, 48>>>();
    conv_gn<<<dim3(256, 2), 192>>>(cw, gg, gb);
    final_mul<<<9216, 256>>>(x, out);
}

// round 10
// speedup vs baseline: 1.3897x; 1.3897x over previous
#include <cuda_runtime.h>

// Problem constants
#define NB   16      // batch
#define NC   64      // channels
#define NH   48      // H == W
#define ND   3072    // xLSTM feature dim (C*W)
#define ND4  12288   // 4*D
#define NT   48      // sequence length
#define NROWS 768    // B*T

// ---------------- device scratch (no allocations allowed) ----------------
__device__ float d_pre1[NROWS * ND4];   // 37.75 MB
__device__ float d_pre2[NROWS * ND4];   // 37.75 MB
__device__ float d_gT[2 * ND4 * NB];    // [stack][col][b]  h@R result
__device__ float d_cst[2 * ND * NB];    // [stack][d][b]
__device__ float d_nst[2 * ND * NB];
__device__ float d_mst[2 * ND * NB];
__device__ float d_hT[2 * ND * NB];     // [stack][d][b]
__device__ float d_Y1[NROWS * ND];      // hidden outputs stack 1 [b][t][d]
__device__ float d_Y2[NROWS * ND];      // hidden outputs stack 2
__device__ float d_xh[NB * NC * NH];
__device__ float d_xw[NB * NC * NH];
__device__ float d_sh[NB * NC * NH];
__device__ float d_sw[NB * NC * NH];

// ---------------- packed fp32x2 helpers (Blackwell FFMA2) ----------------
__device__ __forceinline__ unsigned long long pack2(float x, float y) {
    unsigned long long r;
    asm("mov.b64 %0, {%1, %2};" : "=l"(r) : "f"(x), "f"(y));
    return r;
}
__device__ __forceinline__ void fma2(unsigned long long& c, unsigned long long a,
                                     unsigned long long b) {
    asm("fma.rn.f32x2 %0, %1, %2, %0;" : "+l"(c) : "l"(a), "l"(b));
}
__device__ __forceinline__ float2 unpack2(unsigned long long v) {
    float2 f;
    asm("mov.b64 {%0, %1}, %2;" : "=f"(f.x), "=f"(f.y) : "l"(v));
    return f;
}

// ---------------- pre-projection GEMM: pre = X @ W + bias ----------------
// A: [768, 3072] (x viewed flat), W: [3072, 12288], out: [768, 12288]
// 128x128 tile, BK=8, 256 threads, 8x8 microtile via FFMA2.
__global__ void __launch_bounds__(256) sgemm_pre(const float* __restrict__ A,
                                                 const float* __restrict__ Wm,
                                                 const float* __restrict__ bias,
                                                 int which) {
    __shared__ float As[8][128];
    __shared__ float Bs[8][128];
    float* Cout = which ? d_pre2 : d_pre1;

    int tid = threadIdx.x;
    int bm = blockIdx.y, bn = blockIdx.x;
    int arow = tid >> 1, acol = (tid & 1) << 2;
    int brow = tid >> 5, bcol = (tid & 31) << 2;
    int ty = tid >> 4, tx = tid & 15;

    unsigned long long acc[8][4];
#pragma unroll
    for (int i = 0; i < 8; i++)
#pragma unroll
        for (int j = 0; j < 4; j++) acc[i][j] = 0ull;

    const float* Ap = A + (bm * 128 + arow) * ND + acol;
    const float* Bp = Wm + brow * ND4 + bn * 128 + bcol;

    for (int k0 = 0; k0 < ND; k0 += 8) {
        float4 av = *(const float4*)(Ap + k0);
        float4 bv = *(const float4*)(Bp + (size_t)k0 * ND4);
        As[acol + 0][arow] = av.x;
        As[acol + 1][arow] = av.y;
        As[acol + 2][arow] = av.z;
        As[acol + 3][arow] = av.w;
        *(float4*)&Bs[brow][bcol] = bv;
        __syncthreads();
#pragma unroll
        for (int kk = 0; kk < 8; kk++) {
            float4 a0 = *(const float4*)&As[kk][ty * 8];
            float4 a1 = *(const float4*)&As[kk][ty * 8 + 4];
            ulonglong2 bq0 = *(const ulonglong2*)&Bs[kk][tx * 8];
            ulonglong2 bq1 = *(const ulonglong2*)&Bs[kk][tx * 8 + 4];
            unsigned long long rb[4] = {bq0.x, bq0.y, bq1.x, bq1.y};
            float aa[8] = {a0.x, a0.y, a0.z, a0.w, a1.x, a1.y, a1.z, a1.w};
#pragma unroll
            for (int i = 0; i < 8; i++) {
                unsigned long long ra = pack2(aa[i], aa[i]);
#pragma unroll
                for (int j = 0; j < 4; j++) fma2(acc[i][j], ra, rb[j]);
            }
        }
        __syncthreads();
    }

    int cbase = bn * 128 + tx * 8;
    float4 bb0 = *(const float4*)(bias + cbase);
    float4 bb1 = *(const float4*)(bias + cbase + 4);
#pragma unroll
    for (int i = 0; i < 8; i++) {
        int row = bm * 128 + ty * 8 + i;
        float2 v0 = unpack2(acc[i][0]);
        float2 v1 = unpack2(acc[i][1]);
        float2 v2 = unpack2(acc[i][2]);
        float2 v3 = unpack2(acc[i][3]);
        float4 o0 = make_float4(v0.x + bb0.x, v0.y + bb0.y, v1.x + bb0.z, v1.y + bb0.w);
        float4 o1 = make_float4(v2.x + bb1.x, v2.y + bb1.y, v3.x + bb1.z, v3.y + bb1.w);
        *(float4*)(Cout + (size_t)row * ND4 + cbase) = o0;
        *(float4*)(Cout + (size_t)row * ND4 + cbase + 4) = o1;
    }
}

// ---------------- fused recurrent step GEMM (both stacks): gT = (h @ R)^T ---
// R3 structure (proven 24.7% DRAM at only 2.6 blocks/SM), stacks fused:
// grid = 768: stack = bx&1, col-tile (32 cols) = bx>>1 (0..383).
// block = 256 = 8 warps; warp w = k-slice [w*384, w*384+384).
// h staged in smem per 64-k chunk; inner loop: 1 coalesced R LDG (unroll 8 ->
// MLP 8 toward DRAM) + 4 broadcast LDS.128 + 8 FFMA2.
__global__ void __launch_bounds__(256) step_gemm_f(const float* __restrict__ R1,
                                                   const float* __restrict__ R2) {
    __shared__ float smem[8192];  // 32 KB: h-chunk stage, reused for reduction
    int bx = blockIdx.x;
    int s = bx & 1;
    int cb = bx >> 1;  // 0..383
    const float* __restrict__ R = s ? R2 : R1;
    int tid = threadIdx.x;
    int ksl = tid >> 5;
    int coll = tid & 31;
    int colg = cb * 32 + coll;

    unsigned long long acc[8];
#pragma unroll
    for (int j = 0; j < 8; j++) acc[j] = 0ull;

    const float4* hT4 = (const float4*)(d_hT + s * ND * NB);

    for (int c0 = 0; c0 < 384; c0 += 64) {
        // stage hT chunk: layout [ksl][kk(64)][b(16)]
#pragma unroll
        for (int i = 0; i < 8; i++) {
            int s4 = tid + i * 256;
            int ksl_l = s4 >> 8;
            int rem = s4 & 255;
            ((float4*)smem)[s4] = hT4[ksl_l * 1536 + c0 * 4 + rem];
        }
        __syncthreads();

        const float* rp = R + (size_t)(ksl * 384 + c0) * ND4 + colg;
#pragma unroll 8
        for (int kk = 0; kk < 64; kk++) {
            float rv = __ldcs(rp + (size_t)kk * ND4);
            unsigned long long rr = pack2(rv, rv);
            const ulonglong2* hp = (const ulonglong2*)(smem + ((ksl * 64 + kk) << 4));
            ulonglong2 h0 = hp[0], h1 = hp[1];
            fma2(acc[0], rr, h0.x);
            fma2(acc[1], rr, h0.y);
            fma2(acc[2], rr, h1.x);
            fma2(acc[3], rr, h1.y);
            ulonglong2 h2 = hp[2], h3 = hp[3];
            fma2(acc[4], rr, h2.x);
            fma2(acc[5], rr, h2.y);
            fma2(acc[6], rr, h3.x);
            fma2(acc[7], rr, h3.y);
        }
        __syncthreads();
    }

    // cross-slice reduction via smem
    unsigned long long* sa = (unsigned long long*)smem;
#pragma unroll
    for (int j = 0; j < 8; j++) sa[tid * 8 + j] = acc[j];
    __syncthreads();

    if (tid < 32) {
        int cg2 = cb * 32 + tid;
        float* g = d_gT + (s * ND4 + cg2) * NB;
#pragma unroll
        for (int j = 0; j < 8; j++) {
            float sx = 0.f, sy = 0.f;
#pragma unroll
            for (int sl = 0; sl < 8; sl++) {
                float2 v = unpack2(sa[((sl * 32 + tid) << 3) + j]);
                sx += v.x;
                sy += v.y;
            }
            *(float2*)(g + 2 * j) = make_float2(sx, sy);
        }
    }
}

// ---------------- fused sLSTM gate update (both stacks) ----------------
// thread = (stack, d, b-half of 8). g = gT + pre[:,t,:]; updates states,
// writes hT [stack][d][b] and Y [b][t][d].
__global__ void __launch_bounds__(256) gate_step_f(int t) {
    int idx = blockIdx.x * 256 + threadIdx.x;  // 12288 threads
    int s = idx / (2 * ND);
    int r = idx - s * (2 * ND);
    int d = r >> 1;
    int b0 = (r & 1) << 3;
    const float* __restrict__ pre = s ? d_pre2 : d_pre1;
    float* __restrict__ Y = s ? d_Y2 : d_Y1;

    const int rowstep = (ND * NB) / 4;  // float4 stride between gate blocks
    const float4* gi = (const float4*)(d_gT + (s * ND4 + d) * NB + b0);

    float gv[4][8];
#pragma unroll
    for (int gt = 0; gt < 4; gt++) {
        float4 p0 = gi[gt * rowstep], p1 = gi[gt * rowstep + 1];
        gv[gt][0] = p0.x; gv[gt][1] = p0.y; gv[gt][2] = p0.z; gv[gt][3] = p0.w;
        gv[gt][4] = p1.x; gv[gt][5] = p1.y; gv[gt][6] = p1.z; gv[gt][7] = p1.w;
    }

    int sbase = (s * ND + d) * NB + b0;
    float4 c0 = *(const float4*)(d_cst + sbase);
    float4 c1 = *(const float4*)(d_cst + sbase + 4);
    float4 n0 = *(const float4*)(d_nst + sbase);
    float4 n1 = *(const float4*)(d_nst + sbase + 4);
    float4 m0 = *(const float4*)(d_mst + sbase);
    float4 m1 = *(const float4*)(d_mst + sbase + 4);
    float cv[8] = {c0.x, c0.y, c0.z, c0.w, c1.x, c1.y, c1.z, c1.w};
    float nv[8] = {n0.x, n0.y, n0.z, n0.w, n1.x, n1.y, n1.z, n1.w};
    float mv[8] = {m0.x, m0.y, m0.z, m0.w, m1.x, m1.y, m1.z, m1.w};
    float hv[8];

#pragma unroll
    for (int j = 0; j < 8; j++) {
        int b = b0 + j;
        const float* prow = pre + (size_t)(b * NT + t) * ND4 + d;
        float it = gv[0][j] + prow[0];
        float ft = gv[1][j] + prow[ND];
        float zt = gv[2][j] + prow[2 * ND];
        float ot = gv[3][j] + prow[3 * ND];
        float m = mv[j];
        float mn = fmaxf(ft + m, it);
        float ig = expf(it - mn);
        float fg = expf(ft + m - mn);
        float cn = fg * cv[j] + ig * tanhf(zt);
        float nn = fg * nv[j] + ig;
        float h = cn / (nn + 1e-6f) * (1.0f / (1.0f + expf(-ot)));
        cv[j] = cn;
        nv[j] = nn;
        mv[j] = mn;
        hv[j] = h;
        Y[(size_t)b * (NT * ND) + t * ND + d] = h;
    }

    *(float4*)(d_cst + sbase) = make_float4(cv[0], cv[1], cv[2], cv[3]);
    *(float4*)(d_cst + sbase + 4) = make_float4(cv[4], cv[5], cv[6], cv[7]);
    *(float4*)(d_nst + sbase) = make_float4(nv[0], nv[1], nv[2], nv[3]);
    *(float4*)(d_nst + sbase + 4) = make_float4(nv[4], nv[5], nv[6], nv[7]);
    *(float4*)(d_mst + sbase) = make_float4(mv[0], mv[1], mv[2], mv[3]);
    *(float4*)(d_mst + sbase + 4) = make_float4(mv[4], mv[5], mv[6], mv[7]);
    *(float4*)(d_hT + sbase) = make_float4(hv[0], hv[1], hv[2], hv[3]);
    *(float4*)(d_hT + sbase + 4) = make_float4(hv[4], hv[5], hv[6], hv[7]);
}

__global__ void init_state() {
    int idx = blockIdx.x * 256 + threadIdx.x;  // 98304
    d_cst[idx] = 0.f;
    d_nst[idx] = 0.f;
    d_mst[idx] = 0.f;
    d_hT[idx] = 0.f;
}

// ---------------- spatial means ----------------
// xh[b,c,p] = mean_q Y2[(b*64+c)*2304 + p*48 + q]   (contiguous)
// xw[b,c,p] = mean_q Y1[(b*64+c)*2304 + q*48 + p]   (strided)
__global__ void reduce_means() {
    int bc = blockIdx.x;  // 0..1023 = b*64+c
    int p = threadIdx.x;  // 0..47
    const float* base2 = d_Y2 + bc * 2304;
    const float* base1 = d_Y1 + bc * 2304;
    float s = 0.f;
#pragma unroll 8
    for (int q = 0; q < 48; q++) s += base2[p * 48 + q];
    d_xh[bc * 48 + p] = s * (1.0f / 48.0f);
    float s2 = 0.f;
#pragma unroll 8
    for (int q = 0; q < 48; q++) s2 += base1[q * 48 + p];
    d_xw[bc * 48 + p] = s2 * (1.0f / 48.0f);
}

// ---------------- grouped conv1d + GroupNorm + sigmoid ----------------
__global__ void conv_gn(const float* __restrict__ cw, const float* __restrict__ gamma,
                        const float* __restrict__ beta) {
    int z = blockIdx.y;
    const float* u = z ? d_xw : d_xh;
    float* o = z ? d_sw : d_sh;
    int bidx = blockIdx.x;
    int b = bidx >> 4, g = bidx & 15;
    __shared__ float uin[8][52];
    __shared__ float wsh[4][8][5];
    __shared__ float svals[192];
    __shared__ float stats[2];
    int tid = threadIdx.x;
    int cg = g >> 1;  // conv group of this GN group's channels

    for (int i = tid; i < 384; i += 192) {
        int ci = i / 48, p = i - ci * 48;
        uin[ci][p + 2] = u[(b * NC + cg * 8 + ci) * 48 + p];
    }
    if (tid < 8) {
        uin[tid][0] = 0.f;
        uin[tid][1] = 0.f;
        uin[tid][50] = 0.f;
        uin[tid][51] = 0.f;
    }
    for (int i = tid; i < 160; i += 192) {
        ((float*)wsh)[i] = cw[g * 160 + i];
    }
    __syncthreads();

    int lc = tid / 48, p = tid - lc * 48;
    float v = 0.f;
#pragma unroll
    for (int ci = 0; ci < 8; ci++)
#pragma unroll
        for (int k = 0; k < 5; k++) v += uin[ci][p + k] * wsh[lc][ci][k];

    svals[tid] = v;
    __syncthreads();
    if (tid < 32) {
        float s = 0.f, s2 = 0.f;
#pragma unroll
        for (int i = 0; i < 6; i++) {
            float x = svals[tid + i * 32];
            s += x;
            s2 += x * x;
        }
#pragma unroll
        for (int off = 16; off; off >>= 1) {
            s += __shfl_xor_sync(0xffffffff, s, off);
            s2 += __shfl_xor_sync(0xffffffff, s2, off);
        }
        if (tid == 0) {
            stats[0] = s * (1.0f / 192.0f);
            stats[1] = s2 * (1.0f / 192.0f);
        }
    }
    __syncthreads();
    float mu = stats[0];
    float var = stats[1] - mu * mu;
    int co = 4 * g + lc;
    float xn = (v - mu) * rsqrtf(var + 1e-5f);
    float yv = xn * gamma[co] + beta[co];
    o[(b * NC + co) * 48 + p] = 1.0f / (1.0f + expf(-yv));
}

// ---------------- final: out[b,c,h,w] = sh[b,c,h]*sw[b,c,w]*x ----------------
__global__ void final_mul(const float* __restrict__ x, float* __restrict__ out) {
    int idx = blockIdx.x * 256 + threadIdx.x;  // 2359296 total, exact
    int b = idx / (NC * NH * NH);
    int r = idx - b * (NC * NH * NH);
    int c = r / (NH * NH);
    int r2 = r - c * (NH * NH);
    int h = r2 / NH;
    int w = r2 - h * NH;
    out[idx] = d_sh[(b * NC + c) * 48 + h] * d_sw[(b * NC + c) * 48 + w] * x[idx];
}

// ---------------- launch ----------------
extern "C" void kernel_launch(void* const* d_in, const int* in_sizes, int n_in,
                              void* d_out, int out_size) {
    const float* x  = (const float*)d_in[0];
    const float* W1 = (const float*)d_in[1];
    const float* R1 = (const float*)d_in[2];
    const float* b1 = (const float*)d_in[3];
    const float* W2 = (const float*)d_in[4];
    const float* R2 = (const float*)d_in[5];
    const float* b2 = (const float*)d_in[6];
    const float* cw = (const float*)d_in[7];
    const float* gg = (const float*)d_in[8];
    const float* gb = (const float*)d_in[9];
    float* out = (float*)d_out;

    dim3 gpre(96, 6);
    sgemm_pre<<<gpre, 256>>>(x, W1, b1, 0);
    sgemm_pre<<<gpre, 256>>>(x, W2, b2, 1);

    init_state<<<384, 256>>>();
    for (int t = 0; t < NT; t++) {
        step_gemm_f<<<768, 256>>>(R1, R2);
        gate_step_f<<<48, 256>>>(t);
    }

    reduce_means<<<1024, 48>>>();
    conv_gn<<<dim3(256, 2), 192>>>(cw, gg, gb);
    final_mul<<<9216, 256>>>(x, out);
}

// round 11
// speedup vs baseline: 1.6396x; 1.1798x over previous
#include <cuda_runtime.h>

// Problem constants
#define NB   16      // batch
#define NC   64      // channels
#define NH   48      // H == W
#define ND   3072    // xLSTM feature dim (C*W)
#define ND4  12288   // 4*D
#define NT   48      // sequence length
#define NROWS 768    // B*T

// ---------------- device scratch (no allocations allowed) ----------------
__device__ float d_pre1[NROWS * ND4];     // 37.75 MB
__device__ float d_pre2[NROWS * ND4];     // 37.75 MB
__device__ float d_gTp[2 * 2 * ND4 * NB]; // [khalf][stack][col][b] partial h@R
__device__ float d_cst[2 * ND * NB];      // [stack][d][b]
__device__ float d_nst[2 * ND * NB];
__device__ float d_mst[2 * ND * NB];
__device__ float d_hT[2 * ND * NB];       // [stack][d][b]
__device__ float d_Y1[NROWS * ND];        // hidden outputs stack 1 [b][t][d]
__device__ float d_Y2[NROWS * ND];        // hidden outputs stack 2
__device__ float d_xh[NB * NC * NH];
__device__ float d_xw[NB * NC * NH];
__device__ float d_sh[NB * NC * NH];
__device__ float d_sw[NB * NC * NH];

// ---------------- packed fp32x2 helpers (Blackwell FFMA2) ----------------
__device__ __forceinline__ unsigned long long pack2(float x, float y) {
    unsigned long long r;
    asm("mov.b64 %0, {%1, %2};" : "=l"(r) : "f"(x), "f"(y));
    return r;
}
__device__ __forceinline__ void fma2(unsigned long long& c, unsigned long long a,
                                     unsigned long long b) {
    asm("fma.rn.f32x2 %0, %1, %2, %0;" : "+l"(c) : "l"(a), "l"(b));
}
__device__ __forceinline__ float2 unpack2(unsigned long long v) {
    float2 f;
    asm("mov.b64 {%0, %1}, %2;" : "=f"(f.x), "=f"(f.y) : "l"(v));
    return f;
}

// ---------------- pre-projection GEMM: pre = X @ W + bias ----------------
// A: [768, 3072] (x viewed flat), W: [3072, 12288], out: [768, 12288]
// 128x128 tile, BK=8, 256 threads, 8x8 microtile via FFMA2.
__global__ void __launch_bounds__(256) sgemm_pre(const float* __restrict__ A,
                                                 const float* __restrict__ Wm,
                                                 const float* __restrict__ bias,
                                                 int which) {
    __shared__ float As[8][128];
    __shared__ float Bs[8][128];
    float* Cout = which ? d_pre2 : d_pre1;

    int tid = threadIdx.x;
    int bm = blockIdx.y, bn = blockIdx.x;
    int arow = tid >> 1, acol = (tid & 1) << 2;
    int brow = tid >> 5, bcol = (tid & 31) << 2;
    int ty = tid >> 4, tx = tid & 15;

    unsigned long long acc[8][4];
#pragma unroll
    for (int i = 0; i < 8; i++)
#pragma unroll
        for (int j = 0; j < 4; j++) acc[i][j] = 0ull;

    const float* Ap = A + (bm * 128 + arow) * ND + acol;
    const float* Bp = Wm + brow * ND4 + bn * 128 + bcol;

    for (int k0 = 0; k0 < ND; k0 += 8) {
        float4 av = *(const float4*)(Ap + k0);
        float4 bv = *(const float4*)(Bp + (size_t)k0 * ND4);
        As[acol + 0][arow] = av.x;
        As[acol + 1][arow] = av.y;
        As[acol + 2][arow] = av.z;
        As[acol + 3][arow] = av.w;
        *(float4*)&Bs[brow][bcol] = bv;
        __syncthreads();
#pragma unroll
        for (int kk = 0; kk < 8; kk++) {
            float4 a0 = *(const float4*)&As[kk][ty * 8];
            float4 a1 = *(const float4*)&As[kk][ty * 8 + 4];
            ulonglong2 bq0 = *(const ulonglong2*)&Bs[kk][tx * 8];
            ulonglong2 bq1 = *(const ulonglong2*)&Bs[kk][tx * 8 + 4];
            unsigned long long rb[4] = {bq0.x, bq0.y, bq1.x, bq1.y};
            float aa[8] = {a0.x, a0.y, a0.z, a0.w, a1.x, a1.y, a1.z, a1.w};
#pragma unroll
            for (int i = 0; i < 8; i++) {
                unsigned long long ra = pack2(aa[i], aa[i]);
#pragma unroll
                for (int j = 0; j < 4; j++) fma2(acc[i][j], ra, rb[j]);
            }
        }
        __syncthreads();
    }

    int cbase = bn * 128 + tx * 8;
    float4 bb0 = *(const float4*)(bias + cbase);
    float4 bb1 = *(const float4*)(bias + cbase + 4);
#pragma unroll
    for (int i = 0; i < 8; i++) {
        int row = bm * 128 + ty * 8 + i;
        float2 v0 = unpack2(acc[i][0]);
        float2 v1 = unpack2(acc[i][1]);
        float2 v2 = unpack2(acc[i][2]);
        float2 v3 = unpack2(acc[i][3]);
        float4 o0 = make_float4(v0.x + bb0.x, v0.y + bb0.y, v1.x + bb0.z, v1.y + bb0.w);
        float4 o1 = make_float4(v2.x + bb1.x, v2.y + bb1.y, v3.x + bb1.z, v3.y + bb1.w);
        *(float4*)(Cout + (size_t)row * ND4 + cbase) = o0;
        *(float4*)(Cout + (size_t)row * ND4 + cbase + 4) = o1;
    }
}

// ---------------- fused recurrent step GEMM (both stacks, split-K) --------
// grid = 768: stack = bx&1; (bx>>1) = khalf*192 + coltile(64 cols).
// block = 256 = 8 warps; warp w = k-slice of 192 within its K-half,
// processed in 3 chunks of 64 k staged through smem (as R10).
// Lane handles 2 consecutive cols: per k = 1 LDG.64 (R, __ldcs) +
// 4 broadcast LDS.128 (h) + 16 FFMA2 — halves LSU work per FLOP vs R10.
// Partials -> d_gTp[khalf][stack][col][b]; gate kernel sums the halves.
__global__ void __launch_bounds__(256) step_gemm_f(const float* __restrict__ R1,
                                                   const float* __restrict__ R2) {
    __shared__ float smem[8192];  // 32 KB: h-chunk stage, reused for reduction
    int bx = blockIdx.x;
    int s = bx & 1;
    int tmp = bx >> 1;          // 0..383
    int kh = tmp / 192;         // K-half
    int cb = tmp - kh * 192;    // col-tile 0..191
    const float* __restrict__ R = s ? R2 : R1;
    int tid = threadIdx.x;
    int ksl = tid >> 5;
    int l = tid & 31;
    int col0 = cb * 64 + l * 2;

    unsigned long long a0[8], a1[8];
#pragma unroll
    for (int j = 0; j < 8; j++) { a0[j] = 0ull; a1[j] = 0ull; }

    const float4* hT4 = (const float4*)(d_hT + s * ND * NB);

    for (int c0 = 0; c0 < 192; c0 += 64) {
        // stage hT chunk: layout [ksl][kk(64)][b(16)]
        // warp ksl covers k in [kh*1536 + ksl*192 + c0, +64)
#pragma unroll
        for (int i = 0; i < 8; i++) {
            int s4 = tid + i * 256;
            int ksl_l = s4 >> 8;
            int rem = s4 & 255;
            ((float4*)smem)[s4] = hT4[kh * 6144 + ksl_l * 768 + c0 * 4 + rem];
        }
        __syncthreads();

        const float* rp = R + (size_t)(kh * 1536 + ksl * 192 + c0) * ND4 + col0;
#pragma unroll 8
        for (int kk = 0; kk < 64; kk++) {
            float2 rv = __ldcs((const float2*)(rp + (size_t)kk * ND4));
            unsigned long long rr0 = pack2(rv.x, rv.x);
            unsigned long long rr1 = pack2(rv.y, rv.y);
            const ulonglong2* hp = (const ulonglong2*)(smem + ((ksl * 64 + kk) << 4));
            ulonglong2 h0 = hp[0], h1 = hp[1], h2 = hp[2], h3 = hp[3];
            fma2(a0[0], rr0, h0.x); fma2(a0[1], rr0, h0.y);
            fma2(a0[2], rr0, h1.x); fma2(a0[3], rr0, h1.y);
            fma2(a0[4], rr0, h2.x); fma2(a0[5], rr0, h2.y);
            fma2(a0[6], rr0, h3.x); fma2(a0[7], rr0, h3.y);
            fma2(a1[0], rr1, h0.x); fma2(a1[1], rr1, h0.y);
            fma2(a1[2], rr1, h1.x); fma2(a1[3], rr1, h1.y);
            fma2(a1[4], rr1, h2.x); fma2(a1[5], rr1, h2.y);
            fma2(a1[6], rr1, h3.x); fma2(a1[7], rr1, h3.y);
        }
        __syncthreads();
    }

    // cross-slice reduction via smem: sa[ksl][64 cols][8] u64 = 32 KB exactly
    unsigned long long* sa = (unsigned long long*)smem;
#pragma unroll
    for (int j = 0; j < 8; j++) {
        sa[(ksl * 64 + 2 * l) * 8 + j] = a0[j];
        sa[(ksl * 64 + 2 * l + 1) * 8 + j] = a1[j];
    }
    __syncthreads();

    if (tid < 64) {
        int colg = cb * 64 + tid;
        float* g = d_gTp + ((kh * 2 + s) * ND4 + colg) * NB;
#pragma unroll
        for (int j = 0; j < 8; j++) {
            float sx = 0.f, sy = 0.f;
#pragma unroll
            for (int sl = 0; sl < 8; sl++) {
                float2 v = unpack2(sa[(sl * 64 + tid) * 8 + j]);
                sx += v.x;
                sy += v.y;
            }
            *(float2*)(g + 2 * j) = make_float2(sx, sy);
        }
    }
}

// ---------------- fused sLSTM gate update (both stacks) ----------------
// thread = (stack, d, b-half of 8). g = gTp[0] + gTp[1] + pre[:,t,:];
// updates states, writes hT [stack][d][b] and Y [b][t][d].
__global__ void __launch_bounds__(256) gate_step_f(int t) {
    int idx = blockIdx.x * 256 + threadIdx.x;  // 12288 threads
    int s = idx / (2 * ND);
    int r = idx - s * (2 * ND);
    int d = r >> 1;
    int b0 = (r & 1) << 3;
    const float* __restrict__ pre = s ? d_pre2 : d_pre1;
    float* __restrict__ Y = s ? d_Y2 : d_Y1;

    const int rowstep = (ND * NB) / 4;   // float4 stride between gates
    const int half = (2 * ND4 * NB) / 4; // float4 stride between K-halves
    const float4* gi = (const float4*)(d_gTp + (s * ND4 + d) * NB + b0);

    float gv[4][8];
#pragma unroll
    for (int gt = 0; gt < 4; gt++) {
        float4 p0 = gi[gt * rowstep], p1 = gi[gt * rowstep + 1];
        float4 q0 = gi[gt * rowstep + half], q1 = gi[gt * rowstep + half + 1];
        gv[gt][0] = p0.x + q0.x; gv[gt][1] = p0.y + q0.y;
        gv[gt][2] = p0.z + q0.z; gv[gt][3] = p0.w + q0.w;
        gv[gt][4] = p1.x + q1.x; gv[gt][5] = p1.y + q1.y;
        gv[gt][6] = p1.z + q1.z; gv[gt][7] = p1.w + q1.w;
    }

    int sbase = (s * ND + d) * NB + b0;
    float4 c0 = *(const float4*)(d_cst + sbase);
    float4 c1 = *(const float4*)(d_cst + sbase + 4);
    float4 n0 = *(const float4*)(d_nst + sbase);
    float4 n1 = *(const float4*)(d_nst + sbase + 4);
    float4 m0 = *(const float4*)(d_mst + sbase);
    float4 m1 = *(const float4*)(d_mst + sbase + 4);
    float cv[8] = {c0.x, c0.y, c0.z, c0.w, c1.x, c1.y, c1.z, c1.w};
    float nv[8] = {n0.x, n0.y, n0.z, n0.w, n1.x, n1.y, n1.z, n1.w};
    float mv[8] = {m0.x, m0.y, m0.z, m0.w, m1.x, m1.y, m1.z, m1.w};
    float hv[8];

#pragma unroll
    for (int j = 0; j < 8; j++) {
        int b = b0 + j;
        const float* prow = pre + (size_t)(b * NT + t) * ND4 + d;
        float it = gv[0][j] + prow[0];
        float ft = gv[1][j] + prow[ND];
        float zt = gv[2][j] + prow[2 * ND];
        float ot = gv[3][j] + prow[3 * ND];
        float m = mv[j];
        float mn = fmaxf(ft + m, it);
        float ig = expf(it - mn);
        float fg = expf(ft + m - mn);
        float cn = fg * cv[j] + ig * tanhf(zt);
        float nn = fg * nv[j] + ig;
        float h = cn / (nn + 1e-6f) * (1.0f / (1.0f + expf(-ot)));
        cv[j] = cn;
        nv[j] = nn;
        mv[j] = mn;
        hv[j] = h;
        Y[(size_t)b * (NT * ND) + t * ND + d] = h;
    }

    *(float4*)(d_cst + sbase) = make_float4(cv[0], cv[1], cv[2], cv[3]);
    *(float4*)(d_cst + sbase + 4) = make_float4(cv[4], cv[5], cv[6], cv[7]);
    *(float4*)(d_nst + sbase) = make_float4(nv[0], nv[1], nv[2], nv[3]);
    *(float4*)(d_nst + sbase + 4) = make_float4(nv[4], nv[5], nv[6], nv[7]);
    *(float4*)(d_mst + sbase) = make_float4(mv[0], mv[1], mv[2], mv[3]);
    *(float4*)(d_mst + sbase + 4) = make_float4(mv[4], mv[5], mv[6], mv[7]);
    *(float4*)(d_hT + sbase) = make_float4(hv[0], hv[1], hv[2], hv[3]);
    *(float4*)(d_hT + sbase + 4) = make_float4(hv[4], hv[5], hv[6], hv[7]);
}

__global__ void init_state() {
    int idx = blockIdx.x * 256 + threadIdx.x;  // 98304
    d_cst[idx] = 0.f;
    d_nst[idx] = 0.f;
    d_mst[idx] = 0.f;
    d_hT[idx] = 0.f;
}

// ---------------- spatial means ----------------
// xh[b,c,p] = mean_q Y2[(b*64+c)*2304 + p*48 + q]   (contiguous)
// xw[b,c,p] = mean_q Y1[(b*64+c)*2304 + q*48 + p]   (strided)
__global__ void reduce_means() {
    int bc = blockIdx.x;  // 0..1023 = b*64+c
    int p = threadIdx.x;  // 0..47
    const float* base2 = d_Y2 + bc * 2304;
    const float* base1 = d_Y1 + bc * 2304;
    float s = 0.f;
#pragma unroll 8
    for (int q = 0; q < 48; q++) s += base2[p * 48 + q];
    d_xh[bc * 48 + p] = s * (1.0f / 48.0f);
    float s2 = 0.f;
#pragma unroll 8
    for (int q = 0; q < 48; q++) s2 += base1[q * 48 + p];
    d_xw[bc * 48 + p] = s2 * (1.0f / 48.0f);
}

// ---------------- grouped conv1d + GroupNorm + sigmoid ----------------
__global__ void conv_gn(const float* __restrict__ cw, const float* __restrict__ gamma,
                        const float* __restrict__ beta) {
    int z = blockIdx.y;
    const float* u = z ? d_xw : d_xh;
    float* o = z ? d_sw : d_sh;
    int bidx = blockIdx.x;
    int b = bidx >> 4, g = bidx & 15;
    __shared__ float uin[8][52];
    __shared__ float wsh[4][8][5];
    __shared__ float svals[192];
    __shared__ float stats[2];
    int tid = threadIdx.x;
    int cg = g >> 1;  // conv group of this GN group's channels

    for (int i = tid; i < 384; i += 192) {
        int ci = i / 48, p = i - ci * 48;
        uin[ci][p + 2] = u[(b * NC + cg * 8 + ci) * 48 + p];
    }
    if (tid < 8) {
        uin[tid][0] = 0.f;
        uin[tid][1] = 0.f;
        uin[tid][50] = 0.f;
        uin[tid][51] = 0.f;
    }
    for (int i = tid; i < 160; i += 192) {
        ((float*)wsh)[i] = cw[g * 160 + i];
    }
    __syncthreads();

    int lc = tid / 48, p = tid - lc * 48;
    float v = 0.f;
#pragma unroll
    for (int ci = 0; ci < 8; ci++)
#pragma unroll
        for (int k = 0; k < 5; k++) v += uin[ci][p + k] * wsh[lc][ci][k];

    svals[tid] = v;
    __syncthreads();
    if (tid < 32) {
        float s = 0.f, s2 = 0.f;
#pragma unroll
        for (int i = 0; i < 6; i++) {
            float x = svals[tid + i * 32];
            s += x;
            s2 += x * x;
        }
#pragma unroll
        for (int off = 16; off; off >>= 1) {
            s += __shfl_xor_sync(0xffffffff, s, off);
            s2 += __shfl_xor_sync(0xffffffff, s2, off);
        }
        if (tid == 0) {
            stats[0] = s * (1.0f / 192.0f);
            stats[1] = s2 * (1.0f / 192.0f);
        }
    }
    __syncthreads();
    float mu = stats[0];
    float var = stats[1] - mu * mu;
    int co = 4 * g + lc;
    float xn = (v - mu) * rsqrtf(var + 1e-5f);
    float yv = xn * gamma[co] + beta[co];
    o[(b * NC + co) * 48 + p] = 1.0f / (1.0f + expf(-yv));
}

// ---------------- final: out[b,c,h,w] = sh[b,c,h]*sw[b,c,w]*x ----------------
__global__ void final_mul(const float* __restrict__ x, float* __restrict__ out) {
    int idx = blockIdx.x * 256 + threadIdx.x;  // 2359296 total, exact
    int b = idx / (NC * NH * NH);
    int r = idx - b * (NC * NH * NH);
    int c = r / (NH * NH);
    int r2 = r - c * (NH * NH);
    int h = r2 / NH;
    int w = r2 - h * NH;
    out[idx] = d_sh[(b * NC + c) * 48 + h] * d_sw[(b * NC + c) * 48 + w] * x[idx];
}

// ---------------- launch ----------------
extern "C" void kernel_launch(void* const* d_in, const int* in_sizes, int n_in,
                              void* d_out, int out_size) {
    const float* x  = (const float*)d_in[0];
    const float* W1 = (const float*)d_in[1];
    const float* R1 = (const float*)d_in[2];
    const float* b1 = (const float*)d_in[3];
    const float* W2 = (const float*)d_in[4];
    const float* R2 = (const float*)d_in[5];
    const float* b2 = (const float*)d_in[6];
    const float* cw = (const float*)d_in[7];
    const float* gg = (const float*)d_in[8];
    const float* gb = (const float*)d_in[9];
    float* out = (float*)d_out;

    dim3 gpre(96, 6);
    sgemm_pre<<<gpre, 256>>>(x, W1, b1, 0);
    sgemm_pre<<<gpre, 256>>>(x, W2, b2, 1);

    init_state<<<384, 256>>>();
    for (int t = 0; t < NT; t++) {
        step_gemm_f<<<768, 256>>>(R1, R2);
        gate_step_f<<<48, 256>>>(t);
    }

    reduce_means<<<1024, 48>>>();
    conv_gn<<<dim3(256, 2), 192>>>(cw, gg, gb);
    final_mul<<<9216, 256>>>(x, out);
}